// round 1
// baseline (speedup 1.0000x reference)
#include <cuda_runtime.h>

// Problem constants
#define SEQ   4096
#define BATCH 64
#define DIM   96
#define HID   128
#define NROWS (SEQ*BATCH)       // 262144
#define NC    32                 // CTAs per cell
#define TOTAL_CTAS 64            // 2 cells * NC

// ---------------- scratch (static device globals; no allocation) ----------
__device__ float g_zx0[(size_t)NROWS*1024];   // layer0 input projections (both cells), bias included
__device__ float g_zx1[(size_t)NROWS*1024];   // layer1 input projections
__device__ float g_ys0[(size_t)NROWS*256];    // layer0 output [t][b][2H]
__device__ float g_ys1[(size_t)NROWS*256];    // layer1 output
__device__ float g_hbuf[2][2][2][BATCH*HID];  // [layer][cell][parity][b*128+k]
__device__ int   g_bar[2][SEQ];               // per-layer per-step arrival counters

// ---------------- helpers --------------------------------------------------
__device__ __forceinline__ int ldacq(const int* p) {
    int v;
    asm volatile("ld.acquire.gpu.global.s32 %0, [%1];" : "=r"(v) : "l"(p) : "memory");
    return v;
}
__device__ __forceinline__ float sigm(float x) {
    return 1.f / (1.f + __expf(-x));
}
__device__ __forceinline__ float tanh_s(float x) {
    // safe for large |x|: exp overflow -> inf -> 1 - 0 = 1
    float e = __expf(2.f * x);
    return 1.f - 2.f / (e + 1.f);
}

// ---------------- init: zero barriers + h buffers --------------------------
__global__ void init_kernel() {
    int tid = blockIdx.x * blockDim.x + threadIdx.x;
    int nthr = gridDim.x * blockDim.x;
    int nbar = 2 * SEQ;
    for (int i = tid; i < nbar; i += nthr) ((int*)g_bar)[i] = 0;
    int nh = 2 * 2 * 2 * BATCH * HID;
    for (int i = tid; i < nh; i += nthr) ((float*)g_hbuf)[i] = 0.f;
}

// ---------------- input-projection GEMM ------------------------------------
// Z[row][n] = bias[n] + sum_k A[row][k] * W[n][k],  n in [0,1024)
// n < 512 -> forward-cell weights, n >= 512 -> backward-cell weights.
// Block tile 128(M) x 64(N), K-tile 16, 256 threads, 8x4 microtile.
template<int K, int LAYER>
__global__ void __launch_bounds__(256) gemm_kernel(
    const float* __restrict__ Aext,
    const float* __restrict__ Wf, const float* __restrict__ Wb,
    const float* __restrict__ bf, const float* __restrict__ bb)
{
    __shared__ float As[16][132];
    __shared__ float Bs[16][68];

    const float* A = (LAYER == 0) ? Aext : (const float*)g_ys0;
    float*       Z = (LAYER == 0) ? g_zx0 : g_zx1;

    int tid  = threadIdx.x;
    int nblk = blockIdx.x;        // 0..15
    int mblk = blockIdx.y;        // 0..2047
    int m0 = mblk * 128;
    int n0 = nblk * 64;

    const float* W    = (n0 < 512) ? (Wf + (size_t)n0 * K) : (Wb + (size_t)(n0 - 512) * K);
    const float* bias = (n0 < 512) ? (bf + n0) : (bb + (n0 - 512));

    int ty = tid >> 4;            // 0..15 : rows ty*8..ty*8+7
    int tx = tid & 15;            // 0..15 : cols tx*4..tx*4+3

    float acc[8][4];
#pragma unroll
    for (int i = 0; i < 8; i++)
#pragma unroll
        for (int j = 0; j < 4; j++) acc[i][j] = 0.f;

    for (int k0 = 0; k0 < K; k0 += 16) {
        // A tile: 128 rows x 16 k = 512 float4, 2 per thread, transposed into As[k][row]
#pragma unroll
        for (int i = 0; i < 2; i++) {
            int q  = tid + i * 256;
            int r  = q >> 2;
            int kq = q & 3;
            float4 a = *(const float4*)(A + (size_t)(m0 + r) * K + k0 + kq * 4);
            As[kq * 4 + 0][r] = a.x;
            As[kq * 4 + 1][r] = a.y;
            As[kq * 4 + 2][r] = a.z;
            As[kq * 4 + 3][r] = a.w;
        }
        // B tile: 64 n x 16 k = 256 float4, 1 per thread, transposed into Bs[k][n]
        {
            int q  = tid;
            int n  = q >> 2;
            int kq = q & 3;
            float4 w = *(const float4*)(W + (size_t)n * K + k0 + kq * 4);
            Bs[kq * 4 + 0][n] = w.x;
            Bs[kq * 4 + 1][n] = w.y;
            Bs[kq * 4 + 2][n] = w.z;
            Bs[kq * 4 + 3][n] = w.w;
        }
        __syncthreads();
#pragma unroll
        for (int kk = 0; kk < 16; kk++) {
            float a0[8], b0[4];
            *(float4*)&a0[0] = *(const float4*)&As[kk][ty * 8];
            *(float4*)&a0[4] = *(const float4*)&As[kk][ty * 8 + 4];
            *(float4*)&b0[0] = *(const float4*)&Bs[kk][tx * 4];
#pragma unroll
            for (int i = 0; i < 8; i++)
#pragma unroll
                for (int j = 0; j < 4; j++) acc[i][j] += a0[i] * b0[j];
        }
        __syncthreads();
    }

    float4 bv = *(const float4*)(bias + tx * 4);
#pragma unroll
    for (int i = 0; i < 8; i++) {
        float4 o;
        o.x = acc[i][0] + bv.x;
        o.y = acc[i][1] + bv.y;
        o.z = acc[i][2] + bv.z;
        o.w = acc[i][3] + bv.w;
        *(float4*)(Z + (size_t)(m0 + ty * 8 + i) * 1024 + n0 + tx * 4) = o;
    }
}

// ---------------- recurrence -----------------------------------------------
// Grid = 64 CTAs (cell = blockIdx.x/32, p = blockIdx.x%32), 256 threads.
// CTA owns hidden units [p*4, p*4+4). Thread (b = tid>>2, u = tid&3) computes
// all 4 gates of unit p*4+u for batch b; c lives in a register for all 4096 steps.
// h exchanged via L2-resident double buffer + per-step global spin barrier.
template<int LAYER>
__global__ void __launch_bounds__(256) recur_kernel(
    const float* __restrict__ whhf, const float* __restrict__ whhb)
{
    __shared__ float hs[BATCH][132];
    __shared__ float ws[16][132];

    const float* zx = (LAYER == 0) ? g_zx0 : g_zx1;
    float*       ys = (LAYER == 0) ? g_ys0 : g_ys1;

    int tid  = threadIdx.x;
    int cell = blockIdx.x >> 5;
    int p    = blockIdx.x & 31;
    const float* whh = cell ? whhb : whhf;

    // load this CTA's 16 Whh rows (4 gates x 4 units), 128 k each
    for (int q = tid; q < 512; q += 256) {       // 512 float4s
        int r  = q >> 5;                          // local row 0..15 (= gate*4+u)
        int k4 = q & 31;
        int g  = r >> 2, u = r & 3;
        int j  = g * 128 + p * 4 + u;
        *(float4*)&ws[r][k4 * 4] = *(const float4*)(whh + (size_t)j * 128 + k4 * 4);
    }

    int b = tid >> 2;
    int u = tid & 3;
    int nglob = cell * 512 + p * 4 + u;          // gate-0 column in zx
    float c = 0.f;

    float* hb0 = &g_hbuf[LAYER][cell][0][0];
    float* hb1 = &g_hbuf[LAYER][cell][1][0];
    int*   bar = &g_bar[LAYER][0];

    __syncthreads();

    for (int t = 0; t < SEQ; t++) {
        // issue zx loads early (HBM latency overlaps h reload)
        const float* zrow = zx + ((size_t)t * BATCH + b) * 1024 + nglob;
        float zi = __ldg(zrow);
        float zf = __ldg(zrow + 128);
        float zg = __ldg(zrow + 256);
        float zo = __ldg(zrow + 384);

        // reload full h_t (written by all CTAs of this cell) from L2, bypassing L1
        const float4* hsrc = (const float4*)((t & 1) ? hb1 : hb0);
#pragma unroll
        for (int i = 0; i < 8; i++) {
            int q = tid + i * 256;               // 0..2047 float4s
            float4 h4 = __ldcg(hsrc + q);
            *(float4*)&hs[q >> 5][(q & 31) * 4] = h4;
        }
        __syncthreads();

        float4 ai = {0,0,0,0}, af = ai, ag = ai, ao = ai;
        const float* hr = &hs[b][0];
        const float* w0 = &ws[u][0];
        const float* w1 = &ws[4 + u][0];
        const float* w2 = &ws[8 + u][0];
        const float* w3 = &ws[12 + u][0];
#pragma unroll
        for (int k = 0; k < 128; k += 4) {
            float4 h4 = *(const float4*)(hr + k);
            float4 w;
            w = *(const float4*)(w0 + k);
            ai.x += h4.x * w.x; ai.y += h4.y * w.y; ai.z += h4.z * w.z; ai.w += h4.w * w.w;
            w = *(const float4*)(w1 + k);
            af.x += h4.x * w.x; af.y += h4.y * w.y; af.z += h4.z * w.z; af.w += h4.w * w.w;
            w = *(const float4*)(w2 + k);
            ag.x += h4.x * w.x; ag.y += h4.y * w.y; ag.z += h4.z * w.z; ag.w += h4.w * w.w;
            w = *(const float4*)(w3 + k);
            ao.x += h4.x * w.x; ao.y += h4.y * w.y; ao.z += h4.z * w.z; ao.w += h4.w * w.w;
        }
        zi += (ai.x + ai.y) + (ai.z + ai.w);
        zf += (af.x + af.y) + (af.z + af.w);
        zg += (ag.x + ag.y) + (ag.z + ag.w);
        zo += (ao.x + ao.y) + (ao.z + ao.w);

        float ig = sigm(zi);
        float fg = sigm(zf);
        float gg = tanh_s(zg);
        float og = sigm(zo);
        c = fg * c + ig * gg;
        float h = og * tanh_s(c);

        float* hdst = (t & 1) ? hb0 : hb1;       // parity (t+1)&1
        hdst[b * 128 + p * 4 + u] = h;
        ys[((size_t)t * BATCH + b) * 256 + cell * 128 + p * 4 + u] = h;

        __syncthreads();
        if (tid == 0) {
            __threadfence();
            atomicAdd(&bar[t], 1);
            while (ldacq(&bar[t]) < TOTAL_CTAS) { }
        }
        __syncthreads();
    }
}

// ---------------- final FC + sigmoid ---------------------------------------
__global__ void __launch_bounds__(256) fc_kernel(
    const float* __restrict__ fcw, const float* __restrict__ fcb,
    float* __restrict__ out)
{
    int gtid = blockIdx.x * blockDim.x + threadIdx.x;
    int row  = gtid >> 5;
    int lane = gtid & 31;
    if (row >= NROWS) return;
    const float* y = g_ys1 + (size_t)row * 256;
    float s = 0.f;
#pragma unroll
    for (int i = 0; i < 8; i++) {
        int idx = lane + i * 32;
        s += y[idx] * __ldg(fcw + idx);
    }
#pragma unroll
    for (int o = 16; o; o >>= 1) s += __shfl_xor_sync(0xffffffffu, s, o);
    if (lane == 0) out[row] = 1.f / (1.f + __expf(-(s + fcb[0])));
}

// ---------------- launch ----------------------------------------------------
extern "C" void kernel_launch(void* const* d_in, const int* in_sizes, int n_in,
                              void* d_out, int out_size)
{
    const float* x     = (const float*)d_in[0];
    const float* wih0f = (const float*)d_in[1];
    const float* whh0f = (const float*)d_in[2];
    const float* b0f   = (const float*)d_in[3];
    const float* wih0b = (const float*)d_in[4];
    const float* whh0b = (const float*)d_in[5];
    const float* b0b   = (const float*)d_in[6];
    const float* wih1f = (const float*)d_in[7];
    const float* whh1f = (const float*)d_in[8];
    const float* b1f   = (const float*)d_in[9];
    const float* wih1b = (const float*)d_in[10];
    const float* whh1b = (const float*)d_in[11];
    const float* b1b   = (const float*)d_in[12];
    const float* fcw   = (const float*)d_in[13];
    const float* fcb   = (const float*)d_in[14];
    float* out = (float*)d_out;

    init_kernel<<<64, 256>>>();

    dim3 ggrid(16, NROWS / 128);
    gemm_kernel<DIM, 0><<<ggrid, 256>>>(x, wih0f, wih0b, b0f, b0b);
    recur_kernel<0><<<TOTAL_CTAS, 256>>>(whh0f, whh0b);

    gemm_kernel<256, 1><<<ggrid, 256>>>(nullptr, wih1f, wih1b, b1f, b1b);
    recur_kernel<1><<<TOTAL_CTAS, 256>>>(whh1f, whh1b);

    fc_kernel<<<(NROWS * 32) / 256, 256>>>(fcw, fcb, out);
}

// round 2
// speedup vs baseline: 1.0099x; 1.0099x over previous
#include <cuda_runtime.h>

// Problem constants
#define SEQ   4096
#define BATCH 64
#define DIM   96
#define HID   128
#define NROWS (SEQ*BATCH)       // 262144
#define NC    32                 // CTAs per cell
#define TOTAL_CTAS 64            // 2 cells * NC

// ---------------- scratch (static device globals; no allocation) ----------
__device__ float g_zx0[(size_t)NROWS*1024];   // layer0 input projections (both cells), bias included
__device__ float g_zx1[(size_t)NROWS*1024];   // layer1 input projections
__device__ float g_ys0[(size_t)NROWS*256];    // layer0 output [t][b][2H]
__device__ float g_ys1[(size_t)NROWS*256];    // layer1 output
__device__ float g_hbuf[2][2][2][BATCH*HID];  // [layer][cell][parity][b*128+k]
__device__ int   g_bar[2][SEQ];               // per-layer per-step arrival counters

// ---------------- helpers --------------------------------------------------
__device__ __forceinline__ int ldacq(const int* p) {
    int v;
    asm volatile("ld.acquire.gpu.global.s32 %0, [%1];" : "=r"(v) : "l"(p) : "memory");
    return v;
}
__device__ __forceinline__ float sigm(float x) {
    return 1.f / (1.f + __expf(-x));
}
__device__ __forceinline__ float tanh_s(float x) {
    // safe for large |x|: exp overflow -> inf -> 1 - 0 = 1
    float e = __expf(2.f * x);
    return 1.f - 2.f / (e + 1.f);
}

// ---------------- init: zero barriers + h buffers --------------------------
__global__ void init_kernel() {
    int tid = blockIdx.x * blockDim.x + threadIdx.x;
    int nthr = gridDim.x * blockDim.x;
    int nbar = 2 * SEQ;
    for (int i = tid; i < nbar; i += nthr) ((int*)g_bar)[i] = 0;
    int nh = 2 * 2 * 2 * BATCH * HID;
    for (int i = tid; i < nh; i += nthr) ((float*)g_hbuf)[i] = 0.f;
}

// ---------------- input-projection GEMM ------------------------------------
// Z[row][n] = bias[n] + sum_k A[row][k] * W[n][k],  n in [0,1024)
// n < 512 -> forward-cell weights, n >= 512 -> backward-cell weights.
// Block tile 128(M) x 64(N), K-tile 16, 256 threads, 8x4 microtile.
template<int K, int LAYER>
__global__ void __launch_bounds__(256) gemm_kernel(
    const float* __restrict__ Aext,
    const float* __restrict__ Wf, const float* __restrict__ Wb,
    const float* __restrict__ bf, const float* __restrict__ bb)
{
    __shared__ float As[16][132];
    __shared__ float Bs[16][68];

    const float* A = (LAYER == 0) ? Aext : (const float*)g_ys0;
    float*       Z = (LAYER == 0) ? g_zx0 : g_zx1;

    int tid  = threadIdx.x;
    int nblk = blockIdx.x;        // 0..15
    int mblk = blockIdx.y;        // 0..2047
    int m0 = mblk * 128;
    int n0 = nblk * 64;

    const float* W    = (n0 < 512) ? (Wf + (size_t)n0 * K) : (Wb + (size_t)(n0 - 512) * K);
    const float* bias = (n0 < 512) ? (bf + n0) : (bb + (n0 - 512));

    int ty = tid >> 4;            // 0..15 : rows ty*8..ty*8+7
    int tx = tid & 15;            // 0..15 : cols tx*4..tx*4+3

    float acc[8][4];
#pragma unroll
    for (int i = 0; i < 8; i++)
#pragma unroll
        for (int j = 0; j < 4; j++) acc[i][j] = 0.f;

    for (int k0 = 0; k0 < K; k0 += 16) {
        // A tile: 128 rows x 16 k = 512 float4, 2 per thread, transposed into As[k][row]
#pragma unroll
        for (int i = 0; i < 2; i++) {
            int q  = tid + i * 256;
            int r  = q >> 2;
            int kq = q & 3;
            float4 a = *(const float4*)(A + (size_t)(m0 + r) * K + k0 + kq * 4);
            As[kq * 4 + 0][r] = a.x;
            As[kq * 4 + 1][r] = a.y;
            As[kq * 4 + 2][r] = a.z;
            As[kq * 4 + 3][r] = a.w;
        }
        // B tile: 64 n x 16 k = 256 float4, 1 per thread, transposed into Bs[k][n]
        {
            int q  = tid;
            int n  = q >> 2;
            int kq = q & 3;
            float4 w = *(const float4*)(W + (size_t)n * K + k0 + kq * 4);
            Bs[kq * 4 + 0][n] = w.x;
            Bs[kq * 4 + 1][n] = w.y;
            Bs[kq * 4 + 2][n] = w.z;
            Bs[kq * 4 + 3][n] = w.w;
        }
        __syncthreads();
#pragma unroll
        for (int kk = 0; kk < 16; kk++) {
            float a0[8], b0[4];
            *(float4*)&a0[0] = *(const float4*)&As[kk][ty * 8];
            *(float4*)&a0[4] = *(const float4*)&As[kk][ty * 8 + 4];
            *(float4*)&b0[0] = *(const float4*)&Bs[kk][tx * 4];
#pragma unroll
            for (int i = 0; i < 8; i++)
#pragma unroll
                for (int j = 0; j < 4; j++) acc[i][j] += a0[i] * b0[j];
        }
        __syncthreads();
    }

    float4 bv = *(const float4*)(bias + tx * 4);
#pragma unroll
    for (int i = 0; i < 8; i++) {
        float4 o;
        o.x = acc[i][0] + bv.x;
        o.y = acc[i][1] + bv.y;
        o.z = acc[i][2] + bv.z;
        o.w = acc[i][3] + bv.w;
        *(float4*)(Z + (size_t)(m0 + ty * 8 + i) * 1024 + n0 + tx * 4) = o;
    }
}

// ---------------- recurrence -----------------------------------------------
// Grid = 64 CTAs (cell = blockIdx.x/32, p = blockIdx.x%32), 256 threads.
// CTA owns hidden units [p*4, p*4+4). Thread (b = tid>>2, u = tid&3) computes
// all 4 gates of unit p*4+u for batch b; c lives in a register for all 4096 steps.
// h exchanged via L2-resident double buffer + per-step global spin barrier.
template<int LAYER>
__global__ void __launch_bounds__(256) recur_kernel(
    const float* __restrict__ whhf, const float* __restrict__ whhb)
{
    __shared__ float hs[BATCH][132];
    __shared__ float ws[16][132];

    const float* zx = (LAYER == 0) ? g_zx0 : g_zx1;
    float*       ys = (LAYER == 0) ? g_ys0 : g_ys1;

    int tid  = threadIdx.x;
    int cell = blockIdx.x >> 5;
    int p    = blockIdx.x & 31;
    const float* whh = cell ? whhb : whhf;

    // load this CTA's 16 Whh rows (4 gates x 4 units), 128 k each
    for (int q = tid; q < 512; q += 256) {       // 512 float4s
        int r  = q >> 5;                          // local row 0..15 (= gate*4+u)
        int k4 = q & 31;
        int g  = r >> 2, u = r & 3;
        int j  = g * 128 + p * 4 + u;
        *(float4*)&ws[r][k4 * 4] = *(const float4*)(whh + (size_t)j * 128 + k4 * 4);
    }

    int b = tid >> 2;
    int u = tid & 3;
    int nglob = cell * 512 + p * 4 + u;          // gate-0 column in zx
    float c = 0.f;

    float* hb0 = &g_hbuf[LAYER][cell][0][0];
    float* hb1 = &g_hbuf[LAYER][cell][1][0];
    int*   bar = &g_bar[LAYER][0];

    __syncthreads();

    for (int t = 0; t < SEQ; t++) {
        // issue zx loads early (HBM latency overlaps h reload)
        const float* zrow = zx + ((size_t)t * BATCH + b) * 1024 + nglob;
        float zi = __ldg(zrow);
        float zf = __ldg(zrow + 128);
        float zg = __ldg(zrow + 256);
        float zo = __ldg(zrow + 384);

        // reload full h_t (written by all CTAs of this cell) from L2, bypassing L1
        const float4* hsrc = (const float4*)((t & 1) ? hb1 : hb0);
#pragma unroll
        for (int i = 0; i < 8; i++) {
            int q = tid + i * 256;               // 0..2047 float4s
            float4 h4 = __ldcg(hsrc + q);
            *(float4*)&hs[q >> 5][(q & 31) * 4] = h4;
        }
        __syncthreads();

        float4 ai = {0,0,0,0}, af = ai, ag = ai, ao = ai;
        const float* hr = &hs[b][0];
        const float* w0 = &ws[u][0];
        const float* w1 = &ws[4 + u][0];
        const float* w2 = &ws[8 + u][0];
        const float* w3 = &ws[12 + u][0];
#pragma unroll
        for (int k = 0; k < 128; k += 4) {
            float4 h4 = *(const float4*)(hr + k);
            float4 w;
            w = *(const float4*)(w0 + k);
            ai.x += h4.x * w.x; ai.y += h4.y * w.y; ai.z += h4.z * w.z; ai.w += h4.w * w.w;
            w = *(const float4*)(w1 + k);
            af.x += h4.x * w.x; af.y += h4.y * w.y; af.z += h4.z * w.z; af.w += h4.w * w.w;
            w = *(const float4*)(w2 + k);
            ag.x += h4.x * w.x; ag.y += h4.y * w.y; ag.z += h4.z * w.z; ag.w += h4.w * w.w;
            w = *(const float4*)(w3 + k);
            ao.x += h4.x * w.x; ao.y += h4.y * w.y; ao.z += h4.z * w.z; ao.w += h4.w * w.w;
        }
        zi += (ai.x + ai.y) + (ai.z + ai.w);
        zf += (af.x + af.y) + (af.z + af.w);
        zg += (ag.x + ag.y) + (ag.z + ag.w);
        zo += (ao.x + ao.y) + (ao.z + ao.w);

        float ig = sigm(zi);
        float fg = sigm(zf);
        float gg = tanh_s(zg);
        float og = sigm(zo);
        c = fg * c + ig * gg;
        float h = og * tanh_s(c);

        float* hdst = (t & 1) ? hb0 : hb1;       // parity (t+1)&1
        hdst[b * 128 + p * 4 + u] = h;
        ys[((size_t)t * BATCH + b) * 256 + cell * 128 + p * 4 + u] = h;

        __syncthreads();
        if (tid == 0) {
            __threadfence();
            atomicAdd(&bar[t], 1);
            while (ldacq(&bar[t]) < TOTAL_CTAS) { }
        }
        __syncthreads();
    }
}

// ---------------- final FC + sigmoid ---------------------------------------
__global__ void __launch_bounds__(256) fc_kernel(
    const float* __restrict__ fcw, const float* __restrict__ fcb,
    float* __restrict__ out)
{
    int gtid = blockIdx.x * blockDim.x + threadIdx.x;
    int row  = gtid >> 5;
    int lane = gtid & 31;
    if (row >= NROWS) return;
    const float* y = g_ys1 + (size_t)row * 256;
    float s = 0.f;
#pragma unroll
    for (int i = 0; i < 8; i++) {
        int idx = lane + i * 32;
        s += y[idx] * __ldg(fcw + idx);
    }
#pragma unroll
    for (int o = 16; o; o >>= 1) s += __shfl_xor_sync(0xffffffffu, s, o);
    if (lane == 0) out[row] = 1.f / (1.f + __expf(-(s + fcb[0])));
}

// ---------------- launch ----------------------------------------------------
extern "C" void kernel_launch(void* const* d_in, const int* in_sizes, int n_in,
                              void* d_out, int out_size)
{
    const float* x     = (const float*)d_in[0];
    const float* wih0f = (const float*)d_in[1];
    const float* whh0f = (const float*)d_in[2];
    const float* b0f   = (const float*)d_in[3];
    const float* wih0b = (const float*)d_in[4];
    const float* whh0b = (const float*)d_in[5];
    const float* b0b   = (const float*)d_in[6];
    const float* wih1f = (const float*)d_in[7];
    const float* whh1f = (const float*)d_in[8];
    const float* b1f   = (const float*)d_in[9];
    const float* wih1b = (const float*)d_in[10];
    const float* whh1b = (const float*)d_in[11];
    const float* b1b   = (const float*)d_in[12];
    const float* fcw   = (const float*)d_in[13];
    const float* fcb   = (const float*)d_in[14];
    float* out = (float*)d_out;

    init_kernel<<<64, 256>>>();

    dim3 ggrid(16, NROWS / 128);
    gemm_kernel<DIM, 0><<<ggrid, 256>>>(x, wih0f, wih0b, b0f, b0b);
    recur_kernel<0><<<TOTAL_CTAS, 256>>>(whh0f, whh0b);

    gemm_kernel<256, 1><<<ggrid, 256>>>(nullptr, wih1f, wih1b, b1f, b1b);
    recur_kernel<1><<<TOTAL_CTAS, 256>>>(whh1f, whh1b);

    fc_kernel<<<(NROWS * 32) / 256, 256>>>(fcw, fcb, out);
}